// round 1
// baseline (speedup 1.0000x reference)
#include <cuda_runtime.h>
#include <cstdint>

// EmbeddingLSQ: out[t, d] = (idx[t]==0) ? 0 : round(clamp(W[d, idx[t]]/a, -8, 7))*a
// where idx[t] = argmax_v x[t, v]  (x is one-hot float32).
//
// x:      [4096, 32000] f32  (one-hot rows)
// weight: [1024, 32000] f32
// alpha:  [1] f32
// out:    [4096, 1024]  f32

#define VOCAB   32000
#define DIM     1024
#define TOKENS  4096
#define NTHREADS 256
// 32000 floats = 8000 uint4... per row as uint4: 32000/4 = 8000? No: uint4 = 4 floats.
// 32000 / 4 = 8000 uint4 per row. 8000 / 256 = 31.25 -> 31 full iters + 64 remainder.
#define U4_PER_ROW (VOCAB / 4)          // 8000
#define FULL_ITERS (U4_PER_ROW / NTHREADS)   // 31
#define REM        (U4_PER_ROW - FULL_ITERS * NTHREADS) // 64

__global__ __launch_bounds__(NTHREADS, 8)
void embedding_lsq_kernel(const float* __restrict__ x,
                          const float* __restrict__ w,
                          const float* __restrict__ alpha,
                          float* __restrict__ out) {
    const int t = blockIdx.x;
    __shared__ int s_idx;
    if (threadIdx.x == 0) s_idx = 0;
    __syncthreads();

    // ---- Phase 1: find the nonzero position in the one-hot row ----
    const uint4* __restrict__ row =
        reinterpret_cast<const uint4*>(x + (size_t)t * VOCAB);

    // Batch loads in groups of 8 for MLP, integer nonzero test.
    #pragma unroll
    for (int base = 0; base < FULL_ITERS; base += 8) {
        uint4 v[8];
        int nload = (FULL_ITERS - base) < 8 ? (FULL_ITERS - base) : 8;
        #pragma unroll
        for (int i = 0; i < 8; i++) {
            if (i < nload) v[i] = row[threadIdx.x + (base + i) * NTHREADS];
        }
        #pragma unroll
        for (int i = 0; i < 8; i++) {
            if (i < nload) {
                if (v[i].x | v[i].y | v[i].z | v[i].w) {
                    int j = threadIdx.x + (base + i) * NTHREADS;
                    int loc = v[i].x ? 0 : (v[i].y ? 1 : (v[i].z ? 2 : 3));
                    s_idx = j * 4 + loc;   // unique writer: row is one-hot
                }
            }
        }
    }
    // remainder: 64 uint4 handled by first 64 threads
    if (threadIdx.x < REM) {
        uint4 v = row[FULL_ITERS * NTHREADS + threadIdx.x];
        if (v.x | v.y | v.z | v.w) {
            int j = FULL_ITERS * NTHREADS + threadIdx.x;
            int loc = v.x ? 0 : (v.y ? 1 : (v.z ? 2 : 3));
            s_idx = j * 4 + loc;
        }
    }
    __syncthreads();

    const int idx = s_idx;
    float4* __restrict__ orow =
        reinterpret_cast<float4*>(out + (size_t)t * DIM);

    if (idx == 0) {
        // PAD token (or argmax==0): output row is zero. d_out is poisoned, must write.
        orow[threadIdx.x] = make_float4(0.f, 0.f, 0.f, 0.f);
        return;
    }

    // ---- Phase 2: gather column idx of weight, LSQ fake-quantize ----
    const float a = __ldg(alpha);
    const int d0 = threadIdx.x * 4;

    float4 r;
    #pragma unroll
    for (int k = 0; k < 4; k++) {
        float wv = __ldg(w + (size_t)(d0 + k) * VOCAB + idx);
        // match reference: round(clip(w/a, -8, 7)) * a, round-half-even
        float q = rintf(fminf(fmaxf(wv / a, -8.0f), 7.0f)) * a;
        (&r.x)[k] = q;
    }
    orow[threadIdx.x] = r;
}

extern "C" void kernel_launch(void* const* d_in, const int* in_sizes, int n_in,
                              void* d_out, int out_size) {
    const float* x     = (const float*)d_in[0];
    const float* w     = (const float*)d_in[1];
    const float* alpha = (const float*)d_in[2];
    float* out = (float*)d_out;

    embedding_lsq_kernel<<<TOKENS, NTHREADS>>>(x, w, alpha, out);
}

// round 4
// speedup vs baseline: 1.4158x; 1.4158x over previous
#include <cuda_runtime.h>
#include <cstdint>

// EmbeddingLSQ: out[t, d] = (idx[t]==0) ? 0 : round(clamp(W[d, idx[t]]/a, -8, 7))*a
// where idx[t] = argmax_v x[t, v]  (x is one-hot float32).
//
// Two-kernel split:
//  K1: early-exit scan of the one-hot rows -> g_idx[] (expected ~56% of x read)
//  K2: scattered gather of W columns + LSQ fake-quant (L2 no longer thrashed by x)

#define VOCAB    32000
#define DIM      1024
#define TOKENS   4096
#define NTHREADS 256
#define U4_PER_ROW (VOCAB / 4)          // 8000 uint4 per row

__device__ int g_idx[TOKENS];

// ---------------- Kernel 1: find the hot index with early exit ----------------
__global__ __launch_bounds__(NTHREADS, 8)
void find_idx_kernel(const float* __restrict__ x) {
    const int t = blockIdx.x;
    __shared__ int s_idx;
    __shared__ int s_found;
    if (threadIdx.x == 0) { s_found = 0; s_idx = 0; }
    __syncthreads();

    const uint4* __restrict__ row =
        reinterpret_cast<const uint4*>(x + (size_t)t * VOCAB);
    volatile int* vflag = &s_found;

    // 32 block-wide iterations cover the row (31.25 actually used); scan in
    // order so the expected scanned fraction is ~(hit_pos + batch)/row.
    // Batch of 2 iterations per flag check keeps 2 LDG.128 in flight/thread.
    for (int base = 0; base < 32; base += 2) {
        if (*vflag) break;
        const int j0 = threadIdx.x + base * NTHREADS;
        const int j1 = j0 + NTHREADS;
        const bool p0 = (j0 < U4_PER_ROW);
        const bool p1 = (j1 < U4_PER_ROW);
        uint4 v0, v1;
        if (p0) v0 = row[j0];
        if (p1) v1 = row[j1];
        if (p0 && (v0.x | v0.y | v0.z | v0.w)) {
            const int loc = v0.x ? 0 : (v0.y ? 1 : (v0.z ? 2 : 3));
            s_idx = j0 * 4 + loc;          // unique writer (one-hot row)
            __threadfence_block();
            *vflag = 1;
        }
        if (p1 && (v1.x | v1.y | v1.z | v1.w)) {
            const int loc = v1.x ? 0 : (v1.y ? 1 : (v1.z ? 2 : 3));
            s_idx = j1 * 4 + loc;
            __threadfence_block();
            *vflag = 1;
        }
    }
    __syncthreads();   // all threads (early-exiters and finder) rendezvous
    if (threadIdx.x == 0) g_idx[t] = s_idx;
}

// ---------------- Kernel 2: gather W[:, idx] and LSQ fake-quantize ----------------
__global__ __launch_bounds__(NTHREADS, 8)
void gather_lsq_kernel(const float* __restrict__ w,
                       const float* __restrict__ alpha,
                       float* __restrict__ out) {
    const int t = blockIdx.x;
    const int idx = g_idx[t];
    float4* __restrict__ orow = reinterpret_cast<float4*>(out + (size_t)t * DIM);

    if (idx == 0) {
        // PAD token: output row is zero (d_out is poisoned, must be written).
        orow[threadIdx.x] = make_float4(0.f, 0.f, 0.f, 0.f);
        return;
    }

    const float a = __ldg(alpha);
    const int d0 = threadIdx.x * 4;

    // 4 scattered 4B loads per thread (stride 128 KB apart) -> high MLP;
    // unique sectors dedup in L2 across tokens now that x isn't streaming.
    float wv[4];
    #pragma unroll
    for (int k = 0; k < 4; k++)
        wv[k] = __ldg(w + (size_t)(d0 + k) * VOCAB + idx);

    float4 r;
    #pragma unroll
    for (int k = 0; k < 4; k++) {
        // match reference: round(clip(w/a, -8, 7)) * a, round-half-even
        (&r.x)[k] = rintf(fminf(fmaxf(wv[k] / a, -8.0f), 7.0f)) * a;
    }
    orow[threadIdx.x] = r;
}

extern "C" void kernel_launch(void* const* d_in, const int* in_sizes, int n_in,
                              void* d_out, int out_size) {
    const float* x     = (const float*)d_in[0];
    const float* w     = (const float*)d_in[1];
    const float* alpha = (const float*)d_in[2];
    float* out = (float*)d_out;

    find_idx_kernel<<<TOKENS, NTHREADS>>>(x);
    gather_lsq_kernel<<<TOKENS, NTHREADS>>>(w, alpha, out);
}

// round 6
// speedup vs baseline: 1.5931x; 1.1252x over previous
#include <cuda_runtime.h>
#include <cstdint>

// EmbeddingLSQ: out[t, d] = (idx[t]==0) ? 0 : round(clamp(W[d, idx[t]]/a, -8, 7))*a
// where idx[t] = argmax_v x[t, v]  (x is one-hot float32).
//
// Pipeline:
//  K1 find_idx : early-exit scan of one-hot rows -> g_idx[]  (also zeroes g_cnt)
//  K2 hist     : bucket tokens by idx>>4 (2000 buckets, 64B vocab span)
//  K3 scan     : exclusive prefix sum of bucket counts
//  K4 scatter  : tokens sorted-by-idx into g_order/g_sidx
//  K5 gather   : warp-coalesced gather of W columns (lanes = 32 sorted tokens),
//                smem transpose, coalesced output writes.
//
// Replay-determinism: g_cnt is zeroed by K1 and rebuilt by K2 every call;
// g_off is rebuilt by K3 every call (K4's atomicAdd mutation is overwritten).

#define VOCAB    32000
#define DIM      1024
#define TOKENS   4096
#define NTHREADS 256
#define U4_PER_ROW (VOCAB / 4)          // 8000 uint4 per row
#define NBUCKETS (VOCAB / 16)           // 2000, each spans 64B of a W row
#define GROUP    32                     // tokens per gather group

__device__ int g_idx[TOKENS];
__device__ int g_cnt[NBUCKETS];
__device__ int g_off[NBUCKETS];
__device__ int g_order[TOKENS];
__device__ int g_sidx[TOKENS];

// ---------------- K1: find the hot index with early exit ----------------
__global__ __launch_bounds__(NTHREADS, 8)
void find_idx_kernel(const float* __restrict__ x) {
    const int t = blockIdx.x;
    // opportunistically zero the histogram counters (4096 blocks >= 2000)
    if (threadIdx.x == 0 && t < NBUCKETS) g_cnt[t] = 0;

    __shared__ int s_idx;
    __shared__ int s_found;
    if (threadIdx.x == 0) { s_found = 0; s_idx = 0; }
    __syncthreads();

    const uint4* __restrict__ row =
        reinterpret_cast<const uint4*>(x + (size_t)t * VOCAB);
    volatile int* vflag = &s_found;

    for (int base = 0; base < 32; base += 2) {
        if (*vflag) break;
        const int j0 = threadIdx.x + base * NTHREADS;
        const int j1 = j0 + NTHREADS;
        const bool p0 = (j0 < U4_PER_ROW);
        const bool p1 = (j1 < U4_PER_ROW);
        uint4 v0, v1;
        if (p0) v0 = row[j0];
        if (p1) v1 = row[j1];
        if (p0 && (v0.x | v0.y | v0.z | v0.w)) {
            const int loc = v0.x ? 0 : (v0.y ? 1 : (v0.z ? 2 : 3));
            s_idx = j0 * 4 + loc;          // unique writer (one-hot row)
            __threadfence_block();
            *vflag = 1;
        }
        if (p1 && (v1.x | v1.y | v1.z | v1.w)) {
            const int loc = v1.x ? 0 : (v1.y ? 1 : (v1.z ? 2 : 3));
            s_idx = j1 * 4 + loc;
            __threadfence_block();
            *vflag = 1;
        }
    }
    __syncthreads();   // rendezvous: finder's s_idx visible to thread 0
    if (threadIdx.x == 0) g_idx[t] = s_idx;
}

// ---------------- K2: histogram by bucket ----------------
__global__ void hist_kernel() {
    const int t = blockIdx.x * blockDim.x + threadIdx.x;
    if (t < TOKENS) atomicAdd(&g_cnt[g_idx[t] >> 4], 1);
}

// ---------------- K3: exclusive scan of 2000 counts (1 block) ----------------
__global__ __launch_bounds__(1024)
void scan_kernel() {
    __shared__ int bufA[2048], bufB[2048];
    const int tid = threadIdx.x;
    for (int i = tid; i < 2048; i += 1024)
        bufA[i] = (i < NBUCKETS) ? g_cnt[i] : 0;
    __syncthreads();
    int* src = bufA; int* dst = bufB;
    for (int d = 1; d < 2048; d <<= 1) {
        for (int i = tid; i < 2048; i += 1024)
            dst[i] = (i >= d) ? (src[i] + src[i - d]) : src[i];
        __syncthreads();
        int* tmp = src; src = dst; dst = tmp;
    }
    for (int i = tid; i < 2048; i += 1024)
        if (i < NBUCKETS) g_off[i] = (i == 0) ? 0 : src[i - 1];
}

// ---------------- K4: scatter tokens into sorted order ----------------
__global__ void scatter_kernel() {
    const int t = blockIdx.x * blockDim.x + threadIdx.x;
    if (t < TOKENS) {
        const int idx = g_idx[t];
        const int pos = atomicAdd(&g_off[idx >> 4], 1);
        g_order[pos] = t;
        g_sidx[pos]  = idx;
    }
}

// ---------------- K5: warp-coalesced gather + LSQ + transpose write ----------------
// grid = (TOKENS/GROUP, DIM/128); block = 256 (8 warps).
// Block handles 32 sorted tokens x 128 d-rows, in 4 chunks of 32 d.
__global__ __launch_bounds__(NTHREADS)
void gather_lsq_kernel(const float* __restrict__ w,
                       const float* __restrict__ alpha,
                       float* __restrict__ out) {
    __shared__ int   s_tok[GROUP];
    __shared__ int   s_ix[GROUP];
    __shared__ float tile[32][33];

    const int tid  = threadIdx.x;
    const int warp = tid >> 5;
    const int lane = tid & 31;
    const int gbase = blockIdx.x * GROUP;
    const int dbase0 = blockIdx.y * 128;

    if (tid < GROUP) {
        s_tok[tid] = g_order[gbase + tid];
        s_ix[tid]  = g_sidx[gbase + tid];
    }
    __syncthreads();

    const float a = __ldg(alpha);
    const int   myidx = s_ix[lane];        // lane <-> sorted token (load phase)
    const bool  pad   = (myidx == 0);

    #pragma unroll
    for (int c = 0; c < 4; c++) {
        const int dbase = dbase0 + c * 32;
        // load: warp covers d-rows warp*4..warp*4+3; lanes = 32 nearby vocab cols
        float wv[4];
        #pragma unroll
        for (int r = 0; r < 4; r++)
            wv[r] = __ldg(w + (size_t)(dbase + warp * 4 + r) * VOCAB + myidx);
        #pragma unroll
        for (int r = 0; r < 4; r++) {
            float q = pad ? 0.0f
                          : rintf(fminf(fmaxf(wv[r] / a, -8.0f), 7.0f)) * a;
            tile[warp * 4 + r][lane] = q;
        }
        __syncthreads();
        // write: warp writes tokens 4*warp..4*warp+3, 32 consecutive d each
        #pragma unroll
        for (int r = 0; r < 4; r++) {
            const int tl = warp * 4 + r;
            const int t  = s_tok[tl];
            out[(size_t)t * DIM + dbase + lane] = tile[lane][tl];
        }
        __syncthreads();
    }
}

extern "C" void kernel_launch(void* const* d_in, const int* in_sizes, int n_in,
                              void* d_out, int out_size) {
    const float* x     = (const float*)d_in[0];
    const float* w     = (const float*)d_in[1];
    const float* alpha = (const float*)d_in[2];
    float* out = (float*)d_out;

    find_idx_kernel<<<TOKENS, NTHREADS>>>(x);
    hist_kernel<<<TOKENS / NTHREADS, NTHREADS>>>();
    scan_kernel<<<1, 1024>>>();
    scatter_kernel<<<TOKENS / NTHREADS, NTHREADS>>>();
    dim3 grid(TOKENS / GROUP, DIM / 128);
    gather_lsq_kernel<<<grid, NTHREADS>>>(w, alpha, out);
}